// round 11
// baseline (speedup 1.0000x reference)
#include <cuda_runtime.h>
#include <cuda_bf16.h>
#include <math.h>
#include <stdint.h>

// ---------------- scratch (device globals; no allocations allowed) ----------------
// eval branch
__device__ __nv_bfloat16 g_x1h[16221184];  // [4][124][2044][16] HWC
__device__ __nv_bfloat16 g_x1l[16221184];
__device__ __nv_bfloat16 g_x2h[31334400];  // [4][120][2040][32]
__device__ __nv_bfloat16 g_x2l[31334400];
__device__ float g_c3[60461056];           // 4*64*116*2036
__device__ float g_pool[30171136];         // 4*3712*2032
__device__ float g_lin[520192];
// template branch (separate so branches can run concurrently)
__device__ __nv_bfloat16 t_x1h[8221696];   // [4][124][1036][16]
__device__ __nv_bfloat16 t_x1l[8221696];
__device__ __nv_bfloat16 t_x2h[15851520];  // [4][120][1032][32]
__device__ __nv_bfloat16 t_x2l[15851520];
__device__ float t_c3[30527488];           // 4*64*116*1028
__device__ float t_pool[15204352];         // 4*3712*1024
__device__ float t_lin[262144];
// shared tail
__device__ float g_gru_e[520192];
__device__ float g_gru_t[262144];
__device__ float g_scores[8323072];
__device__ float g_tt[520192];
__device__ uint2 g_wf2h[3200],  g_wf2l[3200];
__device__ uint2 g_wf3h[12800], g_wf3l[12800];
__device__ uint2 t_wf2h[3200],  t_wf2l[3200];
__device__ uint2 t_wf3h[12800], t_wf3l[12800];

// ---------------- packed f32x2 helpers ----------------
__device__ __forceinline__ unsigned long long pack2(float lo, float hi) {
    unsigned long long r;
    asm("mov.b64 %0, {%1, %2};" : "=l"(r) : "f"(lo), "f"(hi));
    return r;
}
__device__ __forceinline__ void unpack2(unsigned long long v, float& lo, float& hi) {
    asm("mov.b64 {%0, %1}, %2;" : "=f"(lo), "=f"(hi) : "l"(v));
}
__device__ __forceinline__ unsigned long long fma2(unsigned long long a,
                                                   unsigned long long b,
                                                   unsigned long long c) {
    unsigned long long d;
    asm("fma.rn.f32x2 %0, %1, %2, %3;" : "=l"(d) : "l"(a), "l"(b), "l"(c));
    return d;
}

// ---------------- MMA / ldmatrix helpers ----------------
__device__ __forceinline__ void mma_bf16(float* c, const unsigned* a, const unsigned* b) {
    asm volatile(
        "mma.sync.aligned.m16n8k16.row.col.f32.bf16.bf16.f32 "
        "{%0,%1,%2,%3},{%4,%5,%6,%7},{%8,%9},{%0,%1,%2,%3};"
        : "+f"(c[0]), "+f"(c[1]), "+f"(c[2]), "+f"(c[3])
        : "r"(a[0]), "r"(a[1]), "r"(a[2]), "r"(a[3]), "r"(b[0]), "r"(b[1]));
}
__device__ __forceinline__ void ldsm_x4(unsigned* r, unsigned saddr) {
    asm volatile("ldmatrix.sync.aligned.m8n8.x4.shared.b16 {%0,%1,%2,%3}, [%4];"
        : "=r"(r[0]), "=r"(r[1]), "=r"(r[2]), "=r"(r[3]) : "r"(saddr));
}
__device__ __forceinline__ unsigned bf16pair(float a, float b) {
    __nv_bfloat162 v;
    v.x = __float2bfloat16(a);
    v.y = __float2bfloat16(b);
    return *(unsigned*)&v;
}

// ---------------- weight B-fragment prep ----------------
__global__ void prep_wfrag_kernel(const float* __restrict__ wt,
                                  uint2* __restrict__ wfh, uint2* __restrict__ wfl,
                                  int CIN, int CO)
{
    int NT = CO >> 3, NCH = CIN >> 4;
    int total = NCH * 25 * NT * 32;
    int idx = blockIdx.x * 256 + threadIdx.x;
    if (idx >= total) return;
    int lane = idx & 31;
    int tmp = idx >> 5;
    int nt = tmp % NT; tmp /= NT;
    int tap = tmp % 25;
    int ch = tmp / 25;
    int g = lane >> 2, t = lane & 3;
    int co = nt * 8 + g;
    int cb = ch * 16;
    float v00 = wt[((size_t)co * CIN + cb + 2*t    ) * 25 + tap];
    float v01 = wt[((size_t)co * CIN + cb + 2*t + 1) * 25 + tap];
    float v10 = wt[((size_t)co * CIN + cb + 8 + 2*t    ) * 25 + tap];
    float v11 = wt[((size_t)co * CIN + cb + 8 + 2*t + 1) * 25 + tap];
    __nv_bfloat16 h00 = __float2bfloat16(v00), h01 = __float2bfloat16(v01);
    __nv_bfloat16 h10 = __float2bfloat16(v10), h11 = __float2bfloat16(v11);
    float l00 = v00 - __bfloat162float(h00), l01 = v01 - __bfloat162float(h01);
    float l10 = v10 - __bfloat162float(h10), l11 = v11 - __bfloat162float(h11);
    uint2 bh, bl;
    { __nv_bfloat162 p; p.x=h00; p.y=h01; bh.x = *(unsigned*)&p; p.x=h10; p.y=h11; bh.y = *(unsigned*)&p; }
    bl.x = bf16pair(l00, l01);
    bl.y = bf16pair(l10, l11);
    wfh[idx] = bh; wfl[idx] = bl;
}

// ---------------- conv1 merged (both branches), scalar fp32 -> split bf16 HWC ----------------
__global__ __launch_bounds__(128)
void conv1_merged_kernel(const float* __restrict__ in0, const float* __restrict__ in1,
                         const float* __restrict__ wt0, const float* __restrict__ wt1,
                         const float* __restrict__ bias0, const float* __restrict__ bias1,
                         __nv_bfloat16* __restrict__ oh0, __nv_bfloat16* __restrict__ ol0,
                         __nv_bfloat16* __restrict__ oh1, __nv_bfloat16* __restrict__ ol1,
                         int Win0_, int Wout0_, int Win1_, int Wout1_)
{
    const int Hin = 128, Hout = 124;
    const int zb = blockIdx.z, br = zb >> 2, b = zb & 3;
    const float* in   = br ? in1 : in0;
    const float* wt   = br ? wt1 : wt0;
    const float* bias = br ? bias1 : bias0;
    __nv_bfloat16* outh = br ? oh1 : oh0;
    __nv_bfloat16* outl = br ? ol1 : ol0;
    const int Win  = br ? Win1_ : Win0_;
    const int Wout = br ? Wout1_ : Wout0_;

    const int tx = threadIdx.x, ty = threadIdx.y;
    const int tid = ty * 16 + tx;
    const int w0 = blockIdx.x * 64;
    const int h0 = blockIdx.y * 8;
    if (w0 >= Wout) return;

    __shared__ __align__(16) float s_in[12][68];
    __shared__ float s_w[16 * 25];
    __shared__ float s_b[16];

    const float* ip = in + ((size_t)b * Hin) * Win;
    for (int idx = tid; idx < 204; idx += 128) {
        int r = idx / 17, j = idx % 17;
        int gh = h0 + r, gw = w0 + 4 * j;
        float4 v = make_float4(0.f, 0.f, 0.f, 0.f);
        if (gh < Hin && gw < Win) v = *(const float4*)&ip[(size_t)gh * Win + gw];
        *(float4*)&s_in[r][4 * j] = v;
    }
    for (int idx = tid; idx < 16 * 25; idx += 128) s_w[idx] = wt[idx];
    if (tid < 16) s_b[tid] = bias[tid];
    __syncthreads();

    float acc[16][4];
    #pragma unroll
    for (int i = 0; i < 16; i++)
        #pragma unroll
        for (int o = 0; o < 4; o++) acc[i][o] = 0.f;

    #pragma unroll
    for (int kh = 0; kh < 5; kh++) {
        float p[8];
        #pragma unroll
        for (int c = 0; c < 8; c++) p[c] = s_in[ty + kh][tx * 4 + c];
        #pragma unroll
        for (int kw = 0; kw < 5; kw++) {
            #pragma unroll
            for (int i = 0; i < 16; i++) {
                float wv = s_w[i * 25 + kh * 5 + kw];
                #pragma unroll
                for (int o = 0; o < 4; o++)
                    acc[i][o] = fmaf(p[kw + o], wv, acc[i][o]);
            }
        }
    }

    const int oh = h0 + ty, ow = w0 + tx * 4;
    if (oh < Hout && ow < Wout) {
        #pragma unroll
        for (int o = 0; o < 4; o++) {
            __align__(16) __nv_bfloat16 hb[16], lb[16];
            #pragma unroll
            for (int i = 0; i < 16; i++) {
                float v = acc[i][o] + s_b[i];
                __nv_bfloat16 h = __float2bfloat16(v);
                hb[i] = h;
                lb[i] = __float2bfloat16(v - __bfloat162float(h));
            }
            size_t base = ((size_t)(b * Hout + oh) * Wout + ow + o) * 16;
            *(uint4*)&outh[base]     = *(uint4*)&hb[0];
            *(uint4*)&outh[base + 8] = *(uint4*)&hb[8];
            *(uint4*)&outl[base]     = *(uint4*)&lb[0];
            *(uint4*)&outl[base + 8] = *(uint4*)&lb[8];
        }
    }
}

// ---------------- conv 5x5 tensor-core merged, tap-loop implicit GEMM (swizzled) ----------------
// NCOH co-half warp-groups: block = 256*NCOH threads; 4 px-mtiles x 2 row-pairs x NCOH.
// Each warp computes NT/NCOH ntiles (kept == 4 for the 64-reg regime).
template<int CIN, int CO, int NCOH, bool OUT_F32>
__global__ __launch_bounds__(256 * NCOH)
void conv5x5_tc_kernel(const __nv_bfloat16* __restrict__ xh0, const __nv_bfloat16* __restrict__ xl0,
                       const __nv_bfloat16* __restrict__ xh1, const __nv_bfloat16* __restrict__ xl1,
                       const uint2* __restrict__ wfh0, const uint2* __restrict__ wfl0,
                       const uint2* __restrict__ wfh1, const uint2* __restrict__ wfl1,
                       const float* __restrict__ bias0, const float* __restrict__ bias1,
                       float* __restrict__ outf0, float* __restrict__ outf1,
                       __nv_bfloat16* __restrict__ oh0, __nv_bfloat16* __restrict__ ol0,
                       __nv_bfloat16* __restrict__ oh1, __nv_bfloat16* __restrict__ ol1,
                       int Hin, int Hout,
                       int Win0_, int Wout0_, int Win1_, int Wout1_)
{
    constexpr int NCH  = CIN / 16;
    constexpr int NT   = CO / 8;
    constexpr int NTPW = NT / NCOH;
    constexpr int NTHR = 256 * NCOH;
    constexpr int COLS = 68;
    constexpr int ROWB = COLS * 32;
    constexpr int PLB  = 8 * ROWB;
    __shared__ __align__(16) unsigned char s_x[2 * PLB];

    const int zb = blockIdx.z, brv = zb >> 2, b = zb & 3;
    const __nv_bfloat16* xh = brv ? xh1 : xh0;
    const __nv_bfloat16* xl = brv ? xl1 : xl0;
    const uint2* wfh = brv ? wfh1 : wfh0;
    const uint2* wfl = brv ? wfl1 : wfl0;
    const float* bias = brv ? bias1 : bias0;
    const int Win  = brv ? Win1_ : Win0_;
    const int Wout = brv ? Wout1_ : Wout0_;

    const int tid = threadIdx.x, warp = tid >> 5, lane = tid & 31;
    const int g = lane >> 2, t = lane & 3;
    const int w0 = blockIdx.x * 64, r0 = blockIdx.y * 4;
    if (w0 >= Wout) return;    // uniform across block: safe w.r.t. barriers
    const int mtile = warp & 3, rh = (warp >> 2) & 1, cohalf = warp >> 3;

    float acc[NTPW][2][4];
    #pragma unroll
    for (int j = 0; j < NTPW; j++)
        #pragma unroll
        for (int r = 0; r < 2; r++)
            #pragma unroll
            for (int q = 0; q < 4; q++) acc[j][r][q] = 0.f;

    const unsigned sbase = (unsigned)__cvta_generic_to_shared(&s_x[0]);
    const int apx  = lane & 15;
    const int hsel = lane >> 4;

    for (int ch = 0; ch < NCH; ch++) {
        __syncthreads();
        for (int i = tid; i < 8 * COLS * 2; i += NTHR) {
            int pl = (i >= 8 * COLS) ? 1 : 0;
            int rc = pl ? (i - 8 * COLS) : i;
            int r = rc / COLS, c = rc % COLS;
            int gw = w0 + c;
            uint4 v0 = make_uint4(0, 0, 0, 0), v1 = make_uint4(0, 0, 0, 0);
            if (gw < Win) {
                const __nv_bfloat16* src = pl ? xl : xh;
                const uint4* p = (const uint4*)&src[((size_t)(b * Hin + r0 + r) * Win + gw) * CIN + ch * 16];
                v0 = p[0]; v1 = p[1];
            }
            unsigned base = pl * PLB + r * ROWB;
            unsigned u0 = (unsigned)(c * 2);     u0 ^= (u0 >> 3) & 1;
            unsigned u1 = (unsigned)(c * 2 + 1); u1 ^= (u1 >> 3) & 1;
            *(uint4*)&s_x[base + u0 * 16] = v0;
            *(uint4*)&s_x[base + u1 * 16] = v1;
        }
        __syncthreads();

        #pragma unroll 1
        for (int tap = 0; tap < 25; tap++) {
            const int kh = tap / 5, kw = tap - kh * 5;
            uint2 bh[NTPW], bl[NTPW];
            #pragma unroll
            for (int j = 0; j < NTPW; j++) {
                int fi = ((ch * 25 + tap) * NT + cohalf * NTPW + j) * 32 + lane;
                bh[j] = wfh[fi];
                bl[j] = wfl[fi];
            }
            const int p = mtile * 16 + apx + kw;
            unsigned u = (unsigned)(p * 2 + hsel);
            u ^= (u >> 3) & 1;
            #pragma unroll
            for (int r = 0; r < 2; r++) {
                const int row = rh * 2 + r + kh;
                unsigned sa = sbase + (unsigned)(row * ROWB) + u * 16;
                unsigned aH[4], aL[4];
                ldsm_x4(aH, sa);
                ldsm_x4(aL, sa + PLB);
                #pragma unroll
                for (int j = 0; j < NTPW; j++) {
                    mma_bf16(acc[j][r], aH, (const unsigned*)&bh[j]);
                    mma_bf16(acc[j][r], aH, (const unsigned*)&bl[j]);
                    mma_bf16(acc[j][r], aL, (const unsigned*)&bh[j]);
                }
            }
        }
    }

    const int pxa = w0 + mtile * 16 + g;
    const int pxb = pxa + 8;
    #pragma unroll
    for (int j = 0; j < NTPW; j++) {
        const int coa = (cohalf * NTPW + j) * 8 + 2 * t;
        const int cob = coa + 1;
        const float bva = bias[coa], bvb = bias[cob];
        #pragma unroll
        for (int r = 0; r < 2; r++) {
            const int hrow = r0 + rh * 2 + r;
            if (OUT_F32) {
                float* outf = brv ? outf1 : outf0;
                if (pxa < Wout) {
                    outf[((size_t)(b * CO + coa) * Hout + hrow) * Wout + pxa] = acc[j][r][0] + bva;
                    outf[((size_t)(b * CO + cob) * Hout + hrow) * Wout + pxa] = acc[j][r][1] + bvb;
                }
                if (pxb < Wout) {
                    outf[((size_t)(b * CO + coa) * Hout + hrow) * Wout + pxb] = acc[j][r][2] + bva;
                    outf[((size_t)(b * CO + cob) * Hout + hrow) * Wout + pxb] = acc[j][r][3] + bvb;
                }
            } else {
                __nv_bfloat16* outh = brv ? oh1 : oh0;
                __nv_bfloat16* outl = brv ? ol1 : ol0;
                if (pxa < Wout) {
                    size_t idx = ((size_t)(b * Hout + hrow) * Wout + pxa) * CO + coa;
                    float v0 = acc[j][r][0] + bva, v1 = acc[j][r][1] + bvb;
                    __nv_bfloat16 h0 = __float2bfloat16(v0), h1 = __float2bfloat16(v1);
                    __nv_bfloat162 hv; hv.x = h0; hv.y = h1;
                    *(__nv_bfloat162*)&outh[idx] = hv;
                    __nv_bfloat162 lv;
                    lv.x = __float2bfloat16(v0 - __bfloat162float(h0));
                    lv.y = __float2bfloat16(v1 - __bfloat162float(h1));
                    *(__nv_bfloat162*)&outl[idx] = lv;
                }
                if (pxb < Wout) {
                    size_t idx = ((size_t)(b * Hout + hrow) * Wout + pxb) * CO + coa;
                    float v0 = acc[j][r][2] + bva, v1 = acc[j][r][3] + bvb;
                    __nv_bfloat16 h0 = __float2bfloat16(v0), h1 = __float2bfloat16(v1);
                    __nv_bfloat162 hv; hv.x = h0; hv.y = h1;
                    *(__nv_bfloat162*)&outh[idx] = hv;
                    __nv_bfloat162 lv;
                    lv.x = __float2bfloat16(v0 - __bfloat162float(h0));
                    lv.y = __float2bfloat16(v1 - __bfloat162float(h1));
                    *(__nv_bfloat162*)&outl[idx] = lv;
                }
            }
        }
    }
}

// ---------------- maxpool merged, vectorized (4 outputs/thread) ----------------
__global__ __launch_bounds__(256)
void maxpool_merged_kernel(const float* __restrict__ in0, float* __restrict__ out0,
                           int Wc0, int Wp0, int n40,
                           const float* __restrict__ in1, float* __restrict__ out1,
                           int Wc1, int Wp1, int n41)
{
    int idx = blockIdx.x * 256 + threadIdx.x;
    const float* in; float* out; int Wc, Wp;
    if (idx < n40) { in = in0; out = out0; Wc = Wc0; Wp = Wp0; }
    else {
        idx -= n40;
        if (idx >= n41) return;
        in = in1; out = out1; Wc = Wc1; Wp = Wp1;
    }
    int wp4 = Wp >> 2;
    int w4 = (idx % wp4) * 4;
    int t = idx / wp4;
    int h = t % 58;
    int bc = t / 58;
    const float* p0 = in + ((size_t)bc * 116 + 2 * h) * Wc + w4;
    const float* p1 = p0 + Wc;
    float4 a0 = *(const float4*)p0, a1 = *(const float4*)(p0 + 4);
    float4 c0 = *(const float4*)p1, c1 = *(const float4*)(p1 + 4);
    float m[8];
    m[0] = fmaxf(a0.x, c0.x); m[1] = fmaxf(a0.y, c0.y);
    m[2] = fmaxf(a0.z, c0.z); m[3] = fmaxf(a0.w, c0.w);
    m[4] = fmaxf(a1.x, c1.x); m[5] = fmaxf(a1.y, c1.y);
    m[6] = fmaxf(a1.z, c1.z); m[7] = fmaxf(a1.w, c1.w);
    float4 o;
    o.x = fmaxf(fmaxf(fmaxf(m[0], m[1]), fmaxf(m[2], m[3])), m[4]);
    o.y = fmaxf(fmaxf(fmaxf(m[1], m[2]), fmaxf(m[3], m[4])), m[5]);
    o.z = fmaxf(fmaxf(fmaxf(m[2], m[3]), fmaxf(m[4], m[5])), m[6]);
    o.w = fmaxf(fmaxf(fmaxf(m[3], m[4]), fmaxf(m[5], m[6])), m[7]);
    *(float4*)&out[(size_t)t * Wp + w4] = o;
}

// ---------------- GEMM merged: C[M,64] = A[M,K] @ W[64,K]^T + bias (f32x2) ----------------
__global__ __launch_bounds__(256)
void gemm_nt64_merged_kernel(const float* __restrict__ A0, const float* __restrict__ W0,
                             const float* __restrict__ b0, float* __restrict__ C0,
                             const float* __restrict__ A1, const float* __restrict__ W1,
                             const float* __restrict__ b1, float* __restrict__ C1,
                             int nb0, int K)
{
    const int bx = blockIdx.x;
    const float *A, *W, *bias; float* C;
    int m0;
    if (bx < nb0) { A = A0; W = W0; bias = b0; C = C0; m0 = bx * 64; }
    else          { A = A1; W = W1; bias = b1; C = C1; m0 = (bx - nb0) * 64; }

    __shared__ __align__(16) float As[16][64];
    __shared__ __align__(16) float Bs[16][64];
    const int tid = threadIdx.x;
    const int tm = tid >> 4, tn = tid & 15;
    const int lm = tid >> 2, lj = (tid & 3) * 4;

    unsigned long long acc2[4][2];
    #pragma unroll
    for (int i = 0; i < 4; i++) { acc2[i][0] = 0ull; acc2[i][1] = 0ull; }

    for (int k0 = 0; k0 < K; k0 += 16) {
        float4 av = *(const float4*)&A[(size_t)(m0 + lm) * K + k0 + lj];
        float4 wv = *(const float4*)&W[(size_t)lm * K + k0 + lj];
        __syncthreads();
        As[lj + 0][lm] = av.x; As[lj + 1][lm] = av.y; As[lj + 2][lm] = av.z; As[lj + 3][lm] = av.w;
        Bs[lj + 0][lm] = wv.x; Bs[lj + 1][lm] = wv.y; Bs[lj + 2][lm] = wv.z; Bs[lj + 3][lm] = wv.w;
        __syncthreads();
        #pragma unroll
        for (int kk = 0; kk < 16; kk++) {
            const unsigned long long* ap = (const unsigned long long*)&As[kk][tm * 4];
            const unsigned long long* bp = (const unsigned long long*)&Bs[kk][tn * 4];
            unsigned long long b01 = bp[0], b23 = bp[1];
            float a0, a1, a2, a3;
            unpack2(ap[0], a0, a1);
            unpack2(ap[1], a2, a3);
            unsigned long long d0 = pack2(a0, a0), d1 = pack2(a1, a1);
            unsigned long long d2 = pack2(a2, a2), d3 = pack2(a3, a3);
            acc2[0][0] = fma2(d0, b01, acc2[0][0]); acc2[0][1] = fma2(d0, b23, acc2[0][1]);
            acc2[1][0] = fma2(d1, b01, acc2[1][0]); acc2[1][1] = fma2(d1, b23, acc2[1][1]);
            acc2[2][0] = fma2(d2, b01, acc2[2][0]); acc2[2][1] = fma2(d2, b23, acc2[2][1]);
            acc2[3][0] = fma2(d3, b01, acc2[3][0]); acc2[3][1] = fma2(d3, b23, acc2[3][1]);
        }
    }
    #pragma unroll
    for (int i = 0; i < 4; i++) {
        float c0, c1, c2, c3;
        unpack2(acc2[i][0], c0, c1);
        unpack2(acc2[i][1], c2, c3);
        float* cp = &C[(size_t)(m0 + tm * 4 + i) * 64 + tn * 4];
        cp[0] = c0 + bias[tn * 4 + 0];
        cp[1] = c1 + bias[tn * 4 + 1];
        cp[2] = c2 + bias[tn * 4 + 2];
        cp[3] = c3 + bias[tn * 4 + 3];
    }
}

// ---------------- GRU merged ----------------
__global__ __launch_bounds__(256)
void gru_merged_kernel(const float* __restrict__ lin0, const float* __restrict__ wih0,
                       const float* __restrict__ whh0, const float* __restrict__ bih0,
                       const float* __restrict__ bhh0, float* __restrict__ out0, int T0, int nb0,
                       const float* __restrict__ lin1, const float* __restrict__ wih1,
                       const float* __restrict__ whh1, const float* __restrict__ bih1,
                       const float* __restrict__ bhh1, float* __restrict__ out1, int T1)
{
    int bx = blockIdx.x;
    const float *lin, *wih, *whh, *bih, *bhh; float* out; int T;
    if (bx < nb0) { lin = lin0; wih = wih0; whh = whh0; bih = bih0; bhh = bhh0; out = out0; T = T0; }
    else { bx -= nb0; lin = lin1; wih = wih1; whh = whh1; bih = bih1; bhh = bhh1; out = out1; T = T1; }

    const int d = threadIdx.x;
    const int ty = threadIdx.y;
    const int row = bx * 4 + ty;
    __shared__ float s_x[4][64];
    __shared__ float s_h[4][64];
    s_h[ty][d] = 0.f;

    const float bir = bih[d], biz = bih[64 + d], bin_ = bih[128 + d];
    const float bhr = bhh[d], bhz = bhh[64 + d], bhn  = bhh[128 + d];

    for (int s = 0; s < 4; s++) {
        __syncthreads();
        s_x[ty][d] = lin[((size_t)s * T + row) * 64 + d];
        __syncthreads();
        float gir = bir, giz = biz, gin = bin_;
        float ghr = bhr, ghz = bhz, ghn = bhn;
        #pragma unroll 8
        for (int k = 0; k < 64; k++) {
            float xv = s_x[ty][k], hv = s_h[ty][k];
            gir = fmaf(xv, wih[d * 64 + k], gir);
            giz = fmaf(xv, wih[(64 + d) * 64 + k], giz);
            gin = fmaf(xv, wih[(128 + d) * 64 + k], gin);
            ghr = fmaf(hv, whh[d * 64 + k], ghr);
            ghz = fmaf(hv, whh[(64 + d) * 64 + k], ghz);
            ghn = fmaf(hv, whh[(128 + d) * 64 + k], ghn);
        }
        float r = 1.f / (1.f + expf(-(gir + ghr)));
        float z = 1.f / (1.f + expf(-(giz + ghz)));
        float n = tanhf(gin + r * ghn);
        float hprev = s_h[ty][d];
        float hn = (1.f - z) * n + z * hprev;
        __syncthreads();
        s_h[ty][d] = hn;
        out[((size_t)s * T + row) * 64 + d] = hn;
    }
}

// ---------------- scores + softmax over e: P[b,t,e] ----------------
__global__ __launch_bounds__(256)
void scores_softmax_kernel(const float* __restrict__ tf, const float* __restrict__ ef,
                           float* __restrict__ P, int Tt, int Te)
{
    const int b = blockIdx.y, t = blockIdx.x, tid = threadIdx.x;
    __shared__ float s_t[64];
    __shared__ float s_red[256];
    if (tid < 64) s_t[tid] = tf[((size_t)b * Tt + t) * 64 + tid];
    __syncthreads();

    float sc[8];
    float lmax = -1e30f;
    #pragma unroll
    for (int ei = 0; ei < 8; ei++) {
        int e = ei * 256 + tid;
        float v = -1e30f;
        if (e < Te) {
            const float4* ep = (const float4*)&ef[((size_t)b * Te + e) * 64];
            float a = 0.f;
            #pragma unroll
            for (int q = 0; q < 16; q++) {
                float4 x = ep[q];
                a = fmaf(x.x, s_t[4 * q + 0], a);
                a = fmaf(x.y, s_t[4 * q + 1], a);
                a = fmaf(x.z, s_t[4 * q + 2], a);
                a = fmaf(x.w, s_t[4 * q + 3], a);
            }
            v = a;
        }
        sc[ei] = v;
        lmax = fmaxf(lmax, v);
    }
    s_red[tid] = lmax; __syncthreads();
    for (int s = 128; s > 0; s >>= 1) { if (tid < s) s_red[tid] = fmaxf(s_red[tid], s_red[tid + s]); __syncthreads(); }
    float m = s_red[0]; __syncthreads();

    float lsum = 0.f;
    #pragma unroll
    for (int ei = 0; ei < 8; ei++) {
        int e = ei * 256 + tid;
        if (e < Te) { sc[ei] = expf(sc[ei] - m); lsum += sc[ei]; }
    }
    s_red[tid] = lsum; __syncthreads();
    for (int s = 128; s > 0; s >>= 1) { if (tid < s) s_red[tid] += s_red[tid + s]; __syncthreads(); }
    float inv = 1.f / s_red[0];

    float* Pr = P + ((size_t)b * Tt + t) * Te;
    #pragma unroll
    for (int ei = 0; ei < 8; ei++) {
        int e = ei * 256 + tid;
        if (e < Te) Pr[e] = sc[ei] * inv;
    }
}

// ---------------- tt[b,e,d] = |sum_t P[b,t,e]*TF[b,t,d] - EF[b,e,d]| ----------------
__global__ __launch_bounds__(256)
void gemm_tt_kernel(const float* __restrict__ P, const float* __restrict__ TF,
                    const float* __restrict__ EF, float* __restrict__ OUT,
                    int Tt, int Te)
{
    __shared__ __align__(16) float As[16][64];
    __shared__ __align__(16) float Bs[16][64];
    const int tid = threadIdx.x;
    const int b = blockIdx.y;
    const int e0 = blockIdx.x * 64;
    const int tm = tid >> 4, tn = tid & 15;
    const int kt = tid >> 4, c4 = (tid & 15) * 4;

    unsigned long long acc2[4][2];
    #pragma unroll
    for (int i = 0; i < 4; i++) { acc2[i][0] = 0ull; acc2[i][1] = 0ull; }

    for (int t0 = 0; t0 < Tt; t0 += 16) {
        float4 av = make_float4(0.f, 0.f, 0.f, 0.f);
        if (e0 + c4 < Te)
            av = *(const float4*)&P[((size_t)b * Tt + t0 + kt) * Te + e0 + c4];
        float4 bv = *(const float4*)&TF[((size_t)b * Tt + t0 + kt) * 64 + c4];
        __syncthreads();
        *(float4*)&As[kt][c4] = av;
        *(float4*)&Bs[kt][c4] = bv;
        __syncthreads();
        #pragma unroll
        for (int kk = 0; kk < 16; kk++) {
            const unsigned long long* ap = (const unsigned long long*)&As[kk][tm * 4];
            const unsigned long long* bp = (const unsigned long long*)&Bs[kk][tn * 4];
            unsigned long long b01 = bp[0], b23 = bp[1];
            float a0, a1, a2, a3;
            unpack2(ap[0], a0, a1);
            unpack2(ap[1], a2, a3);
            unsigned long long d0 = pack2(a0, a0), d1 = pack2(a1, a1);
            unsigned long long d2 = pack2(a2, a2), d3 = pack2(a3, a3);
            acc2[0][0] = fma2(d0, b01, acc2[0][0]); acc2[0][1] = fma2(d0, b23, acc2[0][1]);
            acc2[1][0] = fma2(d1, b01, acc2[1][0]); acc2[1][1] = fma2(d1, b23, acc2[1][1]);
            acc2[2][0] = fma2(d2, b01, acc2[2][0]); acc2[2][1] = fma2(d2, b23, acc2[2][1]);
            acc2[3][0] = fma2(d3, b01, acc2[3][0]); acc2[3][1] = fma2(d3, b23, acc2[3][1]);
        }
    }
    #pragma unroll
    for (int i = 0; i < 4; i++) {
        int e = e0 + tm * 4 + i;
        if (e < Te) {
            float c0, c1, c2, c3;
            unpack2(acc2[i][0], c0, c1);
            unpack2(acc2[i][1], c2, c3);
            size_t off = ((size_t)b * Te + e) * 64 + tn * 4;
            OUT[off + 0] = fabsf(c0 - EF[off + 0]);
            OUT[off + 1] = fabsf(c1 - EF[off + 1]);
            OUT[off + 2] = fabsf(c2 - EF[off + 2]);
            OUT[off + 3] = fabsf(c3 - EF[off + 3]);
        }
    }
}

// ---------------- final: attention pooling + MLP head + softmax ----------------
__global__ __launch_bounds__(256)
void final_kernel(const float* __restrict__ tt, const float* __restrict__ ef,
                  const float* __restrict__ aw, const float* __restrict__ ab,
                  const float* __restrict__ hw, const float* __restrict__ hb,
                  const float* __restrict__ cw, const float* __restrict__ cb,
                  float* __restrict__ out, int Te)
{
    const int b = blockIdx.x, tid = threadIdx.x;
    __shared__ float s_prob[2048];
    __shared__ float s_tmp[256];
    __shared__ float s_red[64];
    __shared__ float s_h[128];

    float loc[8];
    float lmax = -1e30f;
    #pragma unroll
    for (int ei = 0; ei < 8; ei++) {
        int e = ei * 256 + tid;
        float v = -1e30f;
        if (e < Te) {
            const float4* ep = (const float4*)&ef[((size_t)b * Te + e) * 64];
            float a = 0.f;
            #pragma unroll
            for (int q = 0; q < 16; q++) {
                float4 x = ep[q];
                a = fmaf(x.x, aw[4 * q + 0], a);
                a = fmaf(x.y, aw[4 * q + 1], a);
                a = fmaf(x.z, aw[4 * q + 2], a);
                a = fmaf(x.w, aw[4 * q + 3], a);
            }
            v = a + ab[0];
        }
        loc[ei] = v; lmax = fmaxf(lmax, v);
    }
    s_tmp[tid] = lmax; __syncthreads();
    for (int s = 128; s > 0; s >>= 1) { if (tid < s) s_tmp[tid] = fmaxf(s_tmp[tid], s_tmp[tid + s]); __syncthreads(); }
    float m = s_tmp[0]; __syncthreads();

    float lsum = 0.f;
    #pragma unroll
    for (int ei = 0; ei < 8; ei++) {
        int e = ei * 256 + tid;
        if (e < Te) { float ex = expf(loc[ei] - m); s_prob[e] = ex; lsum += ex; }
    }
    s_tmp[tid] = lsum; __syncthreads();
    for (int s = 128; s > 0; s >>= 1) { if (tid < s) s_tmp[tid] += s_tmp[tid + s]; __syncthreads(); }
    float inv = 1.f / s_tmp[0];
    __syncthreads();

    const int d = tid & 63, part = tid >> 6;
    float acc = 0.f;
    for (int e = part; e < Te; e += 4)
        acc = fmaf(tt[((size_t)b * Te + e) * 64 + d], s_prob[e], acc);
    s_tmp[tid] = acc; __syncthreads();
    if (tid < 64)
        s_red[tid] = (s_tmp[tid] + s_tmp[tid + 64] + s_tmp[tid + 128] + s_tmp[tid + 192]) * inv;
    __syncthreads();

    if (tid < 128) {
        float a = hb[tid];
        #pragma unroll 8
        for (int k = 0; k < 64; k++) a = fmaf(s_red[k], hw[tid * 64 + k], a);
        s_h[tid] = fmaxf(a, 0.f);
    }
    __syncthreads();

    if (tid == 0) {
        float l0 = cb[0], l1 = cb[1];
        for (int j = 0; j < 128; j++) {
            l0 = fmaf(s_h[j], cw[j], l0);
            l1 = fmaf(s_h[j], cw[128 + j], l1);
        }
        float mm = fmaxf(l0, l1);
        float e0 = expf(l0 - mm), e1 = expf(l1 - mm);
        float s = e0 + e1;
        out[b * 2 + 0] = e0 / s;
        out[b * 2 + 1] = e1 / s;
    }
}

// ---------------- host driver ----------------
extern "C" void kernel_launch(void* const* d_in, const int* in_sizes, int n_in,
                              void* d_out, int out_size)
{
    (void)in_sizes; (void)n_in; (void)out_size;

    const float* evaluation = (const float*)d_in[0];
    const float* templ      = (const float*)d_in[1];
    const float* e_w1 = (const float*)d_in[2];  const float* e_b1 = (const float*)d_in[3];
    const float* e_w2 = (const float*)d_in[4];  const float* e_b2 = (const float*)d_in[5];
    const float* e_w3 = (const float*)d_in[6];  const float* e_b3 = (const float*)d_in[7];
    const float* el_w = (const float*)d_in[8];  const float* el_b = (const float*)d_in[9];
    const float* eg_wih = (const float*)d_in[10]; const float* eg_whh = (const float*)d_in[11];
    const float* eg_bih = (const float*)d_in[12]; const float* eg_bhh = (const float*)d_in[13];
    const float* t_w1 = (const float*)d_in[14]; const float* t_b1 = (const float*)d_in[15];
    const float* t_w2 = (const float*)d_in[16]; const float* t_b2 = (const float*)d_in[17];
    const float* t_w3 = (const float*)d_in[18]; const float* t_b3 = (const float*)d_in[19];
    const float* tl_w = (const float*)d_in[20]; const float* tl_b = (const float*)d_in[21];
    const float* tg_wih = (const float*)d_in[22]; const float* tg_whh = (const float*)d_in[23];
    const float* tg_bih = (const float*)d_in[24]; const float* tg_bhh = (const float*)d_in[25];
    const float* a_w = (const float*)d_in[26]; const float* a_b = (const float*)d_in[27];
    const float* h_w = (const float*)d_in[28]; const float* h_b = (const float*)d_in[29];
    const float* c_w = (const float*)d_in[30]; const float* c_b = (const float*)d_in[31];

    __nv_bfloat16 *ex1h, *ex1l, *ex2h, *ex2l, *tx1h, *tx1l, *tx2h, *tx2l;
    uint2 *ewf2h, *ewf2l, *ewf3h, *ewf3l, *twf2h, *twf2l, *twf3h, *twf3l;
    float *ec3, *epool, *elin, *tc3, *tpool, *tlin;
    float *pge, *pgt, *psc, *ptt;
    cudaGetSymbolAddress((void**)&ex1h, g_x1h);  cudaGetSymbolAddress((void**)&ex1l, g_x1l);
    cudaGetSymbolAddress((void**)&ex2h, g_x2h);  cudaGetSymbolAddress((void**)&ex2l, g_x2l);
    cudaGetSymbolAddress((void**)&tx1h, t_x1h);  cudaGetSymbolAddress((void**)&tx1l, t_x1l);
    cudaGetSymbolAddress((void**)&tx2h, t_x2h);  cudaGetSymbolAddress((void**)&tx2l, t_x2l);
    cudaGetSymbolAddress((void**)&ewf2h, g_wf2h); cudaGetSymbolAddress((void**)&ewf2l, g_wf2l);
    cudaGetSymbolAddress((void**)&ewf3h, g_wf3h); cudaGetSymbolAddress((void**)&ewf3l, g_wf3l);
    cudaGetSymbolAddress((void**)&twf2h, t_wf2h); cudaGetSymbolAddress((void**)&twf2l, t_wf2l);
    cudaGetSymbolAddress((void**)&twf3h, t_wf3h); cudaGetSymbolAddress((void**)&twf3l, t_wf3l);
    cudaGetSymbolAddress((void**)&ec3,  g_c3);   cudaGetSymbolAddress((void**)&tc3,  t_c3);
    cudaGetSymbolAddress((void**)&epool, g_pool); cudaGetSymbolAddress((void**)&tpool, t_pool);
    cudaGetSymbolAddress((void**)&elin, g_lin);  cudaGetSymbolAddress((void**)&tlin, t_lin);
    cudaGetSymbolAddress((void**)&pge,  g_gru_e);
    cudaGetSymbolAddress((void**)&pgt,  g_gru_t);
    cudaGetSymbolAddress((void**)&psc,  g_scores);
    cudaGetSymbolAddress((void**)&ptt,  g_tt);

    // widths: eval 2048 -> 2044/2040/2036/2032 ; template 1040 -> 1036/1032/1028/1024
    prep_wfrag_kernel<<<(3200 + 255) / 256, 256>>>(e_w2, ewf2h, ewf2l, 16, 32);
    prep_wfrag_kernel<<<(3200 + 255) / 256, 256>>>(t_w2, twf2h, twf2l, 16, 32);
    prep_wfrag_kernel<<<(12800 + 255) / 256, 256>>>(e_w3, ewf3h, ewf3l, 32, 64);
    prep_wfrag_kernel<<<(12800 + 255) / 256, 256>>>(t_w3, twf3h, twf3l, 32, 64);

    conv1_merged_kernel<<<dim3(32, 16, 8), dim3(16, 8)>>>(
        evaluation, templ, e_w1, t_w1, e_b1, t_b1,
        ex1h, ex1l, tx1h, tx1l, 2048, 2044, 1040, 1036);

    conv5x5_tc_kernel<16, 32, 1, false><<<dim3(32, 30, 8), 256>>>(
        ex1h, ex1l, tx1h, tx1l, ewf2h, ewf2l, twf2h, twf2l, e_b2, t_b2,
        nullptr, nullptr, ex2h, ex2l, tx2h, tx2l,
        124, 120, 2044, 2040, 1036, 1032);

    conv5x5_tc_kernel<32, 64, 2, true><<<dim3(32, 29, 8), 512>>>(
        ex2h, ex2l, tx2h, tx2l, ewf3h, ewf3l, twf3h, twf3l, e_b3, t_b3,
        ec3, tc3, nullptr, nullptr, nullptr, nullptr,
        120, 116, 2040, 2036, 1032, 1028);

    const int n40 = (4 * 64 * 58 * 2032) / 4;
    const int n41 = (4 * 64 * 58 * 1024) / 4;
    maxpool_merged_kernel<<<(n40 + n41 + 255) / 256, 256>>>(
        ec3, epool, 2036, 2032, n40, tc3, tpool, 1028, 1024, n41);

    gemm_nt64_merged_kernel<<<127 + 64, 256>>>(
        epool, el_w, el_b, elin, tpool, tl_w, tl_b, tlin, 127, 3712);

    gru_merged_kernel<<<508 + 256, dim3(64, 4)>>>(
        elin, eg_wih, eg_whh, eg_bih, eg_bhh, pge, 2032, 508,
        tlin, tg_wih, tg_whh, tg_bih, tg_bhh, pgt, 1024);

    const int Tt = 1024, Te = 2032;
    scores_softmax_kernel<<<dim3(Tt, 4), 256>>>(pgt, pge, psc, Tt, Te);
    gemm_tt_kernel<<<dim3((Te + 63) / 64, 4), 256>>>(psc, pgt, pge, ptt, Tt, Te);
    final_kernel<<<4, 256>>>(ptt, pge, a_w, a_b, h_w, h_b, c_w, c_b,
                             (float*)d_out, Te);
}

// round 17
// speedup vs baseline: 1.1847x; 1.1847x over previous
#include <cuda_runtime.h>
#include <cuda_bf16.h>
#include <math.h>
#include <stdint.h>

// ---------------- scratch (device globals; no allocations allowed) ----------------
// eval branch
__device__ __nv_bfloat16 g_x1h[16221184];  // [4][124][2044][16] HWC
__device__ __nv_bfloat16 g_x1l[16221184];
__device__ __nv_bfloat16 g_x2h[31334400];  // [4][120][2040][32]
__device__ __nv_bfloat16 g_x2l[31334400];
__device__ float g_c3[60461056];           // 4*64*116*2036
__device__ float g_pool[30171136];         // 4*3712*2032
__device__ float g_lin[520192];
// template branch (separate so branches can run concurrently)
__device__ __nv_bfloat16 t_x1h[8221696];   // [4][124][1036][16]
__device__ __nv_bfloat16 t_x1l[8221696];
__device__ __nv_bfloat16 t_x2h[15851520];  // [4][120][1032][32]
__device__ __nv_bfloat16 t_x2l[15851520];
__device__ float t_c3[30527488];           // 4*64*116*1028
__device__ float t_pool[15204352];         // 4*3712*1024
__device__ float t_lin[262144];
// shared tail
__device__ float g_gru_e[520192];
__device__ float g_gru_t[262144];
__device__ float g_scores[8323072];
__device__ float g_tt[520192];
__device__ uint2 g_wf2h[3200],  g_wf2l[3200];
__device__ uint2 g_wf3h[12800], g_wf3l[12800];
__device__ uint2 t_wf2h[3200],  t_wf2l[3200];
__device__ uint2 t_wf3h[12800], t_wf3l[12800];

// ---------------- packed f32x2 helpers ----------------
__device__ __forceinline__ unsigned long long pack2(float lo, float hi) {
    unsigned long long r;
    asm("mov.b64 %0, {%1, %2};" : "=l"(r) : "f"(lo), "f"(hi));
    return r;
}
__device__ __forceinline__ void unpack2(unsigned long long v, float& lo, float& hi) {
    asm("mov.b64 {%0, %1}, %2;" : "=f"(lo), "=f"(hi) : "l"(v));
}
__device__ __forceinline__ unsigned long long fma2(unsigned long long a,
                                                   unsigned long long b,
                                                   unsigned long long c) {
    unsigned long long d;
    asm("fma.rn.f32x2 %0, %1, %2, %3;" : "=l"(d) : "l"(a), "l"(b), "l"(c));
    return d;
}

// ---------------- MMA / ldmatrix helpers ----------------
__device__ __forceinline__ void mma_bf16(float* c, const unsigned* a, const unsigned* b) {
    asm volatile(
        "mma.sync.aligned.m16n8k16.row.col.f32.bf16.bf16.f32 "
        "{%0,%1,%2,%3},{%4,%5,%6,%7},{%8,%9},{%0,%1,%2,%3};"
        : "+f"(c[0]), "+f"(c[1]), "+f"(c[2]), "+f"(c[3])
        : "r"(a[0]), "r"(a[1]), "r"(a[2]), "r"(a[3]), "r"(b[0]), "r"(b[1]));
}
__device__ __forceinline__ void ldsm_x4(unsigned* r, unsigned saddr) {
    asm volatile("ldmatrix.sync.aligned.m8n8.x4.shared.b16 {%0,%1,%2,%3}, [%4];"
        : "=r"(r[0]), "=r"(r[1]), "=r"(r[2]), "=r"(r[3]) : "r"(saddr));
}
__device__ __forceinline__ unsigned bf16pair(float a, float b) {
    __nv_bfloat162 v;
    v.x = __float2bfloat16(a);
    v.y = __float2bfloat16(b);
    return *(unsigned*)&v;
}

// ---------------- weight B-fragment prep ----------------
__global__ void prep_wfrag_kernel(const float* __restrict__ wt,
                                  uint2* __restrict__ wfh, uint2* __restrict__ wfl,
                                  int CIN, int CO)
{
    int NT = CO >> 3, NCH = CIN >> 4;
    int total = NCH * 25 * NT * 32;
    int idx = blockIdx.x * 256 + threadIdx.x;
    if (idx >= total) return;
    int lane = idx & 31;
    int tmp = idx >> 5;
    int nt = tmp % NT; tmp /= NT;
    int tap = tmp % 25;
    int ch = tmp / 25;
    int g = lane >> 2, t = lane & 3;
    int co = nt * 8 + g;
    int cb = ch * 16;
    float v00 = wt[((size_t)co * CIN + cb + 2*t    ) * 25 + tap];
    float v01 = wt[((size_t)co * CIN + cb + 2*t + 1) * 25 + tap];
    float v10 = wt[((size_t)co * CIN + cb + 8 + 2*t    ) * 25 + tap];
    float v11 = wt[((size_t)co * CIN + cb + 8 + 2*t + 1) * 25 + tap];
    __nv_bfloat16 h00 = __float2bfloat16(v00), h01 = __float2bfloat16(v01);
    __nv_bfloat16 h10 = __float2bfloat16(v10), h11 = __float2bfloat16(v11);
    float l00 = v00 - __bfloat162float(h00), l01 = v01 - __bfloat162float(h01);
    float l10 = v10 - __bfloat162float(h10), l11 = v11 - __bfloat162float(h11);
    uint2 bh, bl;
    { __nv_bfloat162 p; p.x=h00; p.y=h01; bh.x = *(unsigned*)&p; p.x=h10; p.y=h11; bh.y = *(unsigned*)&p; }
    bl.x = bf16pair(l00, l01);
    bl.y = bf16pair(l10, l11);
    wfh[idx] = bh; wfl[idx] = bl;
}

// ---------------- conv1 merged (both branches), scalar fp32 -> split bf16 HWC ----------------
__global__ __launch_bounds__(128)
void conv1_merged_kernel(const float* __restrict__ in0, const float* __restrict__ in1,
                         const float* __restrict__ wt0, const float* __restrict__ wt1,
                         const float* __restrict__ bias0, const float* __restrict__ bias1,
                         __nv_bfloat16* __restrict__ oh0, __nv_bfloat16* __restrict__ ol0,
                         __nv_bfloat16* __restrict__ oh1, __nv_bfloat16* __restrict__ ol1,
                         int Win0_, int Wout0_, int Win1_, int Wout1_)
{
    const int Hin = 128, Hout = 124;
    const int zb = blockIdx.z, br = zb >> 2, b = zb & 3;
    const float* in   = br ? in1 : in0;
    const float* wt   = br ? wt1 : wt0;
    const float* bias = br ? bias1 : bias0;
    __nv_bfloat16* outh = br ? oh1 : oh0;
    __nv_bfloat16* outl = br ? ol1 : ol0;
    const int Win  = br ? Win1_ : Win0_;
    const int Wout = br ? Wout1_ : Wout0_;

    const int tx = threadIdx.x, ty = threadIdx.y;
    const int tid = ty * 16 + tx;
    const int w0 = blockIdx.x * 64;
    const int h0 = blockIdx.y * 8;
    if (w0 >= Wout) return;

    __shared__ __align__(16) float s_in[12][68];
    __shared__ float s_w[16 * 25];
    __shared__ float s_b[16];

    const float* ip = in + ((size_t)b * Hin) * Win;
    for (int idx = tid; idx < 204; idx += 128) {
        int r = idx / 17, j = idx % 17;
        int gh = h0 + r, gw = w0 + 4 * j;
        float4 v = make_float4(0.f, 0.f, 0.f, 0.f);
        if (gh < Hin && gw < Win) v = *(const float4*)&ip[(size_t)gh * Win + gw];
        *(float4*)&s_in[r][4 * j] = v;
    }
    for (int idx = tid; idx < 16 * 25; idx += 128) s_w[idx] = wt[idx];
    if (tid < 16) s_b[tid] = bias[tid];
    __syncthreads();

    float acc[16][4];
    #pragma unroll
    for (int i = 0; i < 16; i++)
        #pragma unroll
        for (int o = 0; o < 4; o++) acc[i][o] = 0.f;

    #pragma unroll
    for (int kh = 0; kh < 5; kh++) {
        float p[8];
        #pragma unroll
        for (int c = 0; c < 8; c++) p[c] = s_in[ty + kh][tx * 4 + c];
        #pragma unroll
        for (int kw = 0; kw < 5; kw++) {
            #pragma unroll
            for (int i = 0; i < 16; i++) {
                float wv = s_w[i * 25 + kh * 5 + kw];
                #pragma unroll
                for (int o = 0; o < 4; o++)
                    acc[i][o] = fmaf(p[kw + o], wv, acc[i][o]);
            }
        }
    }

    const int oh = h0 + ty, ow = w0 + tx * 4;
    if (oh < Hout && ow < Wout) {
        #pragma unroll
        for (int o = 0; o < 4; o++) {
            __align__(16) __nv_bfloat16 hb[16], lb[16];
            #pragma unroll
            for (int i = 0; i < 16; i++) {
                float v = acc[i][o] + s_b[i];
                __nv_bfloat16 h = __float2bfloat16(v);
                hb[i] = h;
                lb[i] = __float2bfloat16(v - __bfloat162float(h));
            }
            size_t base = ((size_t)(b * Hout + oh) * Wout + ow + o) * 16;
            *(uint4*)&outh[base]     = *(uint4*)&hb[0];
            *(uint4*)&outh[base + 8] = *(uint4*)&hb[8];
            *(uint4*)&outl[base]     = *(uint4*)&lb[0];
            *(uint4*)&outl[base + 8] = *(uint4*)&lb[8];
        }
    }
}

// ---------------- conv 5x5 tensor-core merged, tap-loop implicit GEMM (swizzled) ----------------
// R7-proven config: 256 threads, 8 warps = 4 px-mtiles x 2 row-pairs, all NT per warp.
template<int CIN, int CO, bool OUT_F32>
__global__ __launch_bounds__(256)
void conv5x5_tc_kernel(const __nv_bfloat16* __restrict__ xh0, const __nv_bfloat16* __restrict__ xl0,
                       const __nv_bfloat16* __restrict__ xh1, const __nv_bfloat16* __restrict__ xl1,
                       const uint2* __restrict__ wfh0, const uint2* __restrict__ wfl0,
                       const uint2* __restrict__ wfh1, const uint2* __restrict__ wfl1,
                       const float* __restrict__ bias0, const float* __restrict__ bias1,
                       float* __restrict__ outf0, float* __restrict__ outf1,
                       __nv_bfloat16* __restrict__ oh0, __nv_bfloat16* __restrict__ ol0,
                       __nv_bfloat16* __restrict__ oh1, __nv_bfloat16* __restrict__ ol1,
                       int Hin, int Hout,
                       int Win0_, int Wout0_, int Win1_, int Wout1_)
{
    constexpr int NCH  = CIN / 16;
    constexpr int NT   = CO / 8;
    constexpr int COLS = 68;
    constexpr int ROWB = COLS * 32;
    constexpr int PLB  = 8 * ROWB;
    __shared__ __align__(16) unsigned char s_x[2 * PLB];

    const int zb = blockIdx.z, brv = zb >> 2, b = zb & 3;
    const __nv_bfloat16* xh = brv ? xh1 : xh0;
    const __nv_bfloat16* xl = brv ? xl1 : xl0;
    const uint2* wfh = brv ? wfh1 : wfh0;
    const uint2* wfl = brv ? wfl1 : wfl0;
    const float* bias = brv ? bias1 : bias0;
    const int Win  = brv ? Win1_ : Win0_;
    const int Wout = brv ? Wout1_ : Wout0_;

    const int tid = threadIdx.x, warp = tid >> 5, lane = tid & 31;
    const int g = lane >> 2, t = lane & 3;
    const int w0 = blockIdx.x * 64, r0 = blockIdx.y * 4;
    if (w0 >= Wout) return;
    const int mtile = warp & 3, rh = warp >> 2;

    float acc[NT][2][4];
    #pragma unroll
    for (int j = 0; j < NT; j++)
        #pragma unroll
        for (int r = 0; r < 2; r++)
            #pragma unroll
            for (int q = 0; q < 4; q++) acc[j][r][q] = 0.f;

    const unsigned sbase = (unsigned)__cvta_generic_to_shared(&s_x[0]);
    const int apx  = lane & 15;
    const int hsel = lane >> 4;

    for (int ch = 0; ch < NCH; ch++) {
        __syncthreads();
        for (int i = tid; i < 8 * COLS * 2; i += 256) {
            int pl = (i >= 8 * COLS) ? 1 : 0;
            int rc = pl ? (i - 8 * COLS) : i;
            int r = rc / COLS, c = rc % COLS;
            int gw = w0 + c;
            uint4 v0 = make_uint4(0, 0, 0, 0), v1 = make_uint4(0, 0, 0, 0);
            if (gw < Win) {
                const __nv_bfloat16* src = pl ? xl : xh;
                const uint4* p = (const uint4*)&src[((size_t)(b * Hin + r0 + r) * Win + gw) * CIN + ch * 16];
                v0 = p[0]; v1 = p[1];
            }
            unsigned base = pl * PLB + r * ROWB;
            unsigned u0 = (unsigned)(c * 2);     u0 ^= (u0 >> 3) & 1;
            unsigned u1 = (unsigned)(c * 2 + 1); u1 ^= (u1 >> 3) & 1;
            *(uint4*)&s_x[base + u0 * 16] = v0;
            *(uint4*)&s_x[base + u1 * 16] = v1;
        }
        __syncthreads();

        #pragma unroll 1
        for (int tap = 0; tap < 25; tap++) {
            const int kh = tap / 5, kw = tap - kh * 5;
            uint2 bh[NT], bl[NT];
            #pragma unroll
            for (int nt = 0; nt < NT; nt++) {
                int fi = ((ch * 25 + tap) * NT + nt) * 32 + lane;
                bh[nt] = wfh[fi];
                bl[nt] = wfl[fi];
            }
            const int p = mtile * 16 + apx + kw;
            unsigned u = (unsigned)(p * 2 + hsel);
            u ^= (u >> 3) & 1;
            #pragma unroll
            for (int r = 0; r < 2; r++) {
                const int row = rh * 2 + r + kh;
                unsigned sa = sbase + (unsigned)(row * ROWB) + u * 16;
                unsigned aH[4], aL[4];
                ldsm_x4(aH, sa);
                ldsm_x4(aL, sa + PLB);
                #pragma unroll
                for (int nt = 0; nt < NT; nt++) {
                    mma_bf16(acc[nt][r], aH, (const unsigned*)&bh[nt]);
                    mma_bf16(acc[nt][r], aH, (const unsigned*)&bl[nt]);
                    mma_bf16(acc[nt][r], aL, (const unsigned*)&bh[nt]);
                }
            }
        }
    }

    const int pxa = w0 + mtile * 16 + g;
    const int pxb = pxa + 8;
    #pragma unroll
    for (int nt = 0; nt < NT; nt++) {
        const int coa = nt * 8 + 2 * t;
        const int cob = coa + 1;
        const float bva = bias[coa], bvb = bias[cob];
        #pragma unroll
        for (int r = 0; r < 2; r++) {
            const int hrow = r0 + rh * 2 + r;
            if (OUT_F32) {
                float* outf = brv ? outf1 : outf0;
                if (pxa < Wout) {
                    outf[((size_t)(b * CO + coa) * Hout + hrow) * Wout + pxa] = acc[nt][r][0] + bva;
                    outf[((size_t)(b * CO + cob) * Hout + hrow) * Wout + pxa] = acc[nt][r][1] + bvb;
                }
                if (pxb < Wout) {
                    outf[((size_t)(b * CO + coa) * Hout + hrow) * Wout + pxb] = acc[nt][r][2] + bva;
                    outf[((size_t)(b * CO + cob) * Hout + hrow) * Wout + pxb] = acc[nt][r][3] + bvb;
                }
            } else {
                __nv_bfloat16* outh = brv ? oh1 : oh0;
                __nv_bfloat16* outl = brv ? ol1 : ol0;
                if (pxa < Wout) {
                    size_t idx = ((size_t)(b * Hout + hrow) * Wout + pxa) * CO + coa;
                    float v0 = acc[nt][r][0] + bva, v1 = acc[nt][r][1] + bvb;
                    __nv_bfloat16 h0 = __float2bfloat16(v0), h1 = __float2bfloat16(v1);
                    __nv_bfloat162 hv; hv.x = h0; hv.y = h1;
                    *(__nv_bfloat162*)&outh[idx] = hv;
                    __nv_bfloat162 lv;
                    lv.x = __float2bfloat16(v0 - __bfloat162float(h0));
                    lv.y = __float2bfloat16(v1 - __bfloat162float(h1));
                    *(__nv_bfloat162*)&outl[idx] = lv;
                }
                if (pxb < Wout) {
                    size_t idx = ((size_t)(b * Hout + hrow) * Wout + pxb) * CO + coa;
                    float v0 = acc[nt][r][2] + bva, v1 = acc[nt][r][3] + bvb;
                    __nv_bfloat16 h0 = __float2bfloat16(v0), h1 = __float2bfloat16(v1);
                    __nv_bfloat162 hv; hv.x = h0; hv.y = h1;
                    *(__nv_bfloat162*)&outh[idx] = hv;
                    __nv_bfloat162 lv;
                    lv.x = __float2bfloat16(v0 - __bfloat162float(h0));
                    lv.y = __float2bfloat16(v1 - __bfloat162float(h1));
                    *(__nv_bfloat162*)&outl[idx] = lv;
                }
            }
        }
    }
}

// ---------------- maxpool merged, vectorized (4 outputs/thread) ----------------
__global__ __launch_bounds__(256)
void maxpool_merged_kernel(const float* __restrict__ in0, float* __restrict__ out0,
                           int Wc0, int Wp0, int n40,
                           const float* __restrict__ in1, float* __restrict__ out1,
                           int Wc1, int Wp1, int n41)
{
    int idx = blockIdx.x * 256 + threadIdx.x;
    const float* in; float* out; int Wc, Wp;
    if (idx < n40) { in = in0; out = out0; Wc = Wc0; Wp = Wp0; }
    else {
        idx -= n40;
        if (idx >= n41) return;
        in = in1; out = out1; Wc = Wc1; Wp = Wp1;
    }
    int wp4 = Wp >> 2;
    int w4 = (idx % wp4) * 4;
    int t = idx / wp4;
    int h = t % 58;
    int bc = t / 58;
    const float* p0 = in + ((size_t)bc * 116 + 2 * h) * Wc + w4;
    const float* p1 = p0 + Wc;
    float4 a0 = *(const float4*)p0, a1 = *(const float4*)(p0 + 4);
    float4 c0 = *(const float4*)p1, c1 = *(const float4*)(p1 + 4);
    float m[8];
    m[0] = fmaxf(a0.x, c0.x); m[1] = fmaxf(a0.y, c0.y);
    m[2] = fmaxf(a0.z, c0.z); m[3] = fmaxf(a0.w, c0.w);
    m[4] = fmaxf(a1.x, c1.x); m[5] = fmaxf(a1.y, c1.y);
    m[6] = fmaxf(a1.z, c1.z); m[7] = fmaxf(a1.w, c1.w);
    float4 o;
    o.x = fmaxf(fmaxf(fmaxf(m[0], m[1]), fmaxf(m[2], m[3])), m[4]);
    o.y = fmaxf(fmaxf(fmaxf(m[1], m[2]), fmaxf(m[3], m[4])), m[5]);
    o.z = fmaxf(fmaxf(fmaxf(m[2], m[3]), fmaxf(m[4], m[5])), m[6]);
    o.w = fmaxf(fmaxf(fmaxf(m[3], m[4]), fmaxf(m[5], m[6])), m[7]);
    *(float4*)&out[(size_t)t * Wp + w4] = o;
}

// ---------------- GEMM merged: C[M,64] = A[M,K] @ W[64,K]^T + bias (f32x2) ----------------
__global__ __launch_bounds__(256)
void gemm_nt64_merged_kernel(const float* __restrict__ A0, const float* __restrict__ W0,
                             const float* __restrict__ b0, float* __restrict__ C0,
                             const float* __restrict__ A1, const float* __restrict__ W1,
                             const float* __restrict__ b1, float* __restrict__ C1,
                             int nb0, int K)
{
    const int bx = blockIdx.x;
    const float *A, *W, *bias; float* C;
    int m0;
    if (bx < nb0) { A = A0; W = W0; bias = b0; C = C0; m0 = bx * 64; }
    else          { A = A1; W = W1; bias = b1; C = C1; m0 = (bx - nb0) * 64; }

    __shared__ __align__(16) float As[16][64];
    __shared__ __align__(16) float Bs[16][64];
    const int tid = threadIdx.x;
    const int tm = tid >> 4, tn = tid & 15;
    const int lm = tid >> 2, lj = (tid & 3) * 4;

    unsigned long long acc2[4][2];
    #pragma unroll
    for (int i = 0; i < 4; i++) { acc2[i][0] = 0ull; acc2[i][1] = 0ull; }

    for (int k0 = 0; k0 < K; k0 += 16) {
        float4 av = *(const float4*)&A[(size_t)(m0 + lm) * K + k0 + lj];
        float4 wv = *(const float4*)&W[(size_t)lm * K + k0 + lj];
        __syncthreads();
        As[lj + 0][lm] = av.x; As[lj + 1][lm] = av.y; As[lj + 2][lm] = av.z; As[lj + 3][lm] = av.w;
        Bs[lj + 0][lm] = wv.x; Bs[lj + 1][lm] = wv.y; Bs[lj + 2][lm] = wv.z; Bs[lj + 3][lm] = wv.w;
        __syncthreads();
        #pragma unroll
        for (int kk = 0; kk < 16; kk++) {
            const unsigned long long* ap = (const unsigned long long*)&As[kk][tm * 4];
            const unsigned long long* bp = (const unsigned long long*)&Bs[kk][tn * 4];
            unsigned long long b01 = bp[0], b23 = bp[1];
            float a0, a1, a2, a3;
            unpack2(ap[0], a0, a1);
            unpack2(ap[1], a2, a3);
            unsigned long long d0 = pack2(a0, a0), d1 = pack2(a1, a1);
            unsigned long long d2 = pack2(a2, a2), d3 = pack2(a3, a3);
            acc2[0][0] = fma2(d0, b01, acc2[0][0]); acc2[0][1] = fma2(d0, b23, acc2[0][1]);
            acc2[1][0] = fma2(d1, b01, acc2[1][0]); acc2[1][1] = fma2(d1, b23, acc2[1][1]);
            acc2[2][0] = fma2(d2, b01, acc2[2][0]); acc2[2][1] = fma2(d2, b23, acc2[2][1]);
            acc2[3][0] = fma2(d3, b01, acc2[3][0]); acc2[3][1] = fma2(d3, b23, acc2[3][1]);
        }
    }
    #pragma unroll
    for (int i = 0; i < 4; i++) {
        float c0, c1, c2, c3;
        unpack2(acc2[i][0], c0, c1);
        unpack2(acc2[i][1], c2, c3);
        float* cp = &C[(size_t)(m0 + tm * 4 + i) * 64 + tn * 4];
        cp[0] = c0 + bias[tn * 4 + 0];
        cp[1] = c1 + bias[tn * 4 + 1];
        cp[2] = c2 + bias[tn * 4 + 2];
        cp[3] = c3 + bias[tn * 4 + 3];
    }
}

// ---------------- GRU merged ----------------
__global__ __launch_bounds__(256)
void gru_merged_kernel(const float* __restrict__ lin0, const float* __restrict__ wih0,
                       const float* __restrict__ whh0, const float* __restrict__ bih0,
                       const float* __restrict__ bhh0, float* __restrict__ out0, int T0, int nb0,
                       const float* __restrict__ lin1, const float* __restrict__ wih1,
                       const float* __restrict__ whh1, const float* __restrict__ bih1,
                       const float* __restrict__ bhh1, float* __restrict__ out1, int T1)
{
    int bx = blockIdx.x;
    const float *lin, *wih, *whh, *bih, *bhh; float* out; int T;
    if (bx < nb0) { lin = lin0; wih = wih0; whh = whh0; bih = bih0; bhh = bhh0; out = out0; T = T0; }
    else { bx -= nb0; lin = lin1; wih = wih1; whh = whh1; bih = bih1; bhh = bhh1; out = out1; T = T1; }

    const int d = threadIdx.x;
    const int ty = threadIdx.y;
    const int row = bx * 4 + ty;
    __shared__ float s_x[4][64];
    __shared__ float s_h[4][64];
    s_h[ty][d] = 0.f;

    const float bir = bih[d], biz = bih[64 + d], bin_ = bih[128 + d];
    const float bhr = bhh[d], bhz = bhh[64 + d], bhn  = bhh[128 + d];

    for (int s = 0; s < 4; s++) {
        __syncthreads();
        s_x[ty][d] = lin[((size_t)s * T + row) * 64 + d];
        __syncthreads();
        float gir = bir, giz = biz, gin = bin_;
        float ghr = bhr, ghz = bhz, ghn = bhn;
        #pragma unroll 8
        for (int k = 0; k < 64; k++) {
            float xv = s_x[ty][k], hv = s_h[ty][k];
            gir = fmaf(xv, wih[d * 64 + k], gir);
            giz = fmaf(xv, wih[(64 + d) * 64 + k], giz);
            gin = fmaf(xv, wih[(128 + d) * 64 + k], gin);
            ghr = fmaf(hv, whh[d * 64 + k], ghr);
            ghz = fmaf(hv, whh[(64 + d) * 64 + k], ghz);
            ghn = fmaf(hv, whh[(128 + d) * 64 + k], ghn);
        }
        float r = 1.f / (1.f + expf(-(gir + ghr)));
        float z = 1.f / (1.f + expf(-(giz + ghz)));
        float n = tanhf(gin + r * ghn);
        float hprev = s_h[ty][d];
        float hn = (1.f - z) * n + z * hprev;
        __syncthreads();
        s_h[ty][d] = hn;
        out[((size_t)s * T + row) * 64 + d] = hn;
    }
}

// ---------------- scores + softmax over e, 4 t-rows per block ----------------
// P[b,t,e] = softmax_e( tf[b,t,:] . ef[b,e,:] ); ef read once per 4 t-rows.
__global__ __launch_bounds__(256)
void scores_softmax_kernel(const float* __restrict__ tf, const float* __restrict__ ef,
                           float* __restrict__ P, int Tt, int Te)
{
    const int b = blockIdx.y, t0 = blockIdx.x * 4, tid = threadIdx.x;
    __shared__ float s_t[4][64];
    __shared__ float s_red[256];
    {
        int tr = tid >> 6, d = tid & 63;   // 256 threads = 4 rows x 64
        s_t[tr][d] = tf[((size_t)b * Tt + t0 + tr) * 64 + d];
    }
    __syncthreads();

    float sc[4][8];
    #pragma unroll
    for (int ei = 0; ei < 8; ei++) {
        int e = ei * 256 + tid;
        float a0 = 0.f, a1 = 0.f, a2 = 0.f, a3 = 0.f;
        if (e < Te) {
            const float4* ep = (const float4*)&ef[((size_t)b * Te + e) * 64];
            #pragma unroll
            for (int q = 0; q < 16; q++) {
                float4 x = ep[q];
                a0 = fmaf(x.x, s_t[0][4*q+0], a0); a0 = fmaf(x.y, s_t[0][4*q+1], a0);
                a0 = fmaf(x.z, s_t[0][4*q+2], a0); a0 = fmaf(x.w, s_t[0][4*q+3], a0);
                a1 = fmaf(x.x, s_t[1][4*q+0], a1); a1 = fmaf(x.y, s_t[1][4*q+1], a1);
                a1 = fmaf(x.z, s_t[1][4*q+2], a1); a1 = fmaf(x.w, s_t[1][4*q+3], a1);
                a2 = fmaf(x.x, s_t[2][4*q+0], a2); a2 = fmaf(x.y, s_t[2][4*q+1], a2);
                a2 = fmaf(x.z, s_t[2][4*q+2], a2); a2 = fmaf(x.w, s_t[2][4*q+3], a2);
                a3 = fmaf(x.x, s_t[3][4*q+0], a3); a3 = fmaf(x.y, s_t[3][4*q+1], a3);
                a3 = fmaf(x.z, s_t[3][4*q+2], a3); a3 = fmaf(x.w, s_t[3][4*q+3], a3);
            }
        } else {
            a0 = a1 = a2 = a3 = -1e30f;
        }
        sc[0][ei] = a0; sc[1][ei] = a1; sc[2][ei] = a2; sc[3][ei] = a3;
    }

    #pragma unroll 1
    for (int tr = 0; tr < 4; tr++) {
        float lmax = -1e30f;
        #pragma unroll
        for (int ei = 0; ei < 8; ei++) lmax = fmaxf(lmax, sc[tr][ei]);
        __syncthreads();
        s_red[tid] = lmax; __syncthreads();
        for (int s = 128; s > 0; s >>= 1) { if (tid < s) s_red[tid] = fmaxf(s_red[tid], s_red[tid + s]); __syncthreads(); }
        float m = s_red[0]; __syncthreads();

        float lsum = 0.f;
        #pragma unroll
        for (int ei = 0; ei < 8; ei++) {
            int e = ei * 256 + tid;
            if (e < Te) { sc[tr][ei] = expf(sc[tr][ei] - m); lsum += sc[tr][ei]; }
        }
        s_red[tid] = lsum; __syncthreads();
        for (int s = 128; s > 0; s >>= 1) { if (tid < s) s_red[tid] += s_red[tid + s]; __syncthreads(); }
        float inv = 1.f / s_red[0];

        float* Pr = P + ((size_t)b * Tt + t0 + tr) * Te;
        #pragma unroll
        for (int ei = 0; ei < 8; ei++) {
            int e = ei * 256 + tid;
            if (e < Te) Pr[e] = sc[tr][ei] * inv;
        }
    }
}

// ---------------- tt[b,e,d] = |sum_t P[b,t,e]*TF[b,t,d] - EF[b,e,d]| ----------------
__global__ __launch_bounds__(256)
void gemm_tt_kernel(const float* __restrict__ P, const float* __restrict__ TF,
                    const float* __restrict__ EF, float* __restrict__ OUT,
                    int Tt, int Te)
{
    __shared__ __align__(16) float As[16][64];
    __shared__ __align__(16) float Bs[16][64];
    const int tid = threadIdx.x;
    const int b = blockIdx.y;
    const int e0 = blockIdx.x * 64;
    const int tm = tid >> 4, tn = tid & 15;
    const int kt = tid >> 4, c4 = (tid & 15) * 4;

    unsigned long long acc2[4][2];
    #pragma unroll
    for (int i = 0; i < 4; i++) { acc2[i][0] = 0ull; acc2[i][1] = 0ull; }

    for (int t0 = 0; t0 < Tt; t0 += 16) {
        float4 av = make_float4(0.f, 0.f, 0.f, 0.f);
        if (e0 + c4 < Te)
            av = *(const float4*)&P[((size_t)b * Tt + t0 + kt) * Te + e0 + c4];
        float4 bv = *(const float4*)&TF[((size_t)b * Tt + t0 + kt) * 64 + c4];
        __syncthreads();
        *(float4*)&As[kt][c4] = av;
        *(float4*)&Bs[kt][c4] = bv;
        __syncthreads();
        #pragma unroll
        for (int kk = 0; kk < 16; kk++) {
            const unsigned long long* ap = (const unsigned long long*)&As[kk][tm * 4];
            const unsigned long long* bp = (const unsigned long long*)&Bs[kk][tn * 4];
            unsigned long long b01 = bp[0], b23 = bp[1];
            float a0, a1, a2, a3;
            unpack2(ap[0], a0, a1);
            unpack2(ap[1], a2, a3);
            unsigned long long d0 = pack2(a0, a0), d1 = pack2(a1, a1);
            unsigned long long d2 = pack2(a2, a2), d3 = pack2(a3, a3);
            acc2[0][0] = fma2(d0, b01, acc2[0][0]); acc2[0][1] = fma2(d0, b23, acc2[0][1]);
            acc2[1][0] = fma2(d1, b01, acc2[1][0]); acc2[1][1] = fma2(d1, b23, acc2[1][1]);
            acc2[2][0] = fma2(d2, b01, acc2[2][0]); acc2[2][1] = fma2(d2, b23, acc2[2][1]);
            acc2[3][0] = fma2(d3, b01, acc2[3][0]); acc2[3][1] = fma2(d3, b23, acc2[3][1]);
        }
    }
    #pragma unroll
    for (int i = 0; i < 4; i++) {
        int e = e0 + tm * 4 + i;
        if (e < Te) {
            float c0, c1, c2, c3;
            unpack2(acc2[i][0], c0, c1);
            unpack2(acc2[i][1], c2, c3);
            size_t off = ((size_t)b * Te + e) * 64 + tn * 4;
            OUT[off + 0] = fabsf(c0 - EF[off + 0]);
            OUT[off + 1] = fabsf(c1 - EF[off + 1]);
            OUT[off + 2] = fabsf(c2 - EF[off + 2]);
            OUT[off + 3] = fabsf(c3 - EF[off + 3]);
        }
    }
}

// ---------------- final: attention pooling + MLP head + softmax ----------------
__global__ __launch_bounds__(256)
void final_kernel(const float* __restrict__ tt, const float* __restrict__ ef,
                  const float* __restrict__ aw, const float* __restrict__ ab,
                  const float* __restrict__ hw, const float* __restrict__ hb,
                  const float* __restrict__ cw, const float* __restrict__ cb,
                  float* __restrict__ out, int Te)
{
    const int b = blockIdx.x, tid = threadIdx.x;
    __shared__ float s_prob[2048];
    __shared__ float s_tmp[256];
    __shared__ float s_red[64];
    __shared__ float s_h[128];

    float loc[8];
    float lmax = -1e30f;
    #pragma unroll
    for (int ei = 0; ei < 8; ei++) {
        int e = ei * 256 + tid;
        float v = -1e30f;
        if (e < Te) {
            const float4* ep = (const float4*)&ef[((size_t)b * Te + e) * 64];
            float a = 0.f;
            #pragma unroll
            for (int q = 0; q < 16; q++) {
                float4 x = ep[q];
                a = fmaf(x.x, aw[4 * q + 0], a);
                a = fmaf(x.y, aw[4 * q + 1], a);
                a = fmaf(x.z, aw[4 * q + 2], a);
                a = fmaf(x.w, aw[4 * q + 3], a);
            }
            v = a + ab[0];
        }
        loc[ei] = v; lmax = fmaxf(lmax, v);
    }
    s_tmp[tid] = lmax; __syncthreads();
    for (int s = 128; s > 0; s >>= 1) { if (tid < s) s_tmp[tid] = fmaxf(s_tmp[tid], s_tmp[tid + s]); __syncthreads(); }
    float m = s_tmp[0]; __syncthreads();

    float lsum = 0.f;
    #pragma unroll
    for (int ei = 0; ei < 8; ei++) {
        int e = ei * 256 + tid;
        if (e < Te) { float ex = expf(loc[ei] - m); s_prob[e] = ex; lsum += ex; }
    }
    s_tmp[tid] = lsum; __syncthreads();
    for (int s = 128; s > 0; s >>= 1) { if (tid < s) s_tmp[tid] += s_tmp[tid + s]; __syncthreads(); }
    float inv = 1.f / s_tmp[0];
    __syncthreads();

    const int d = tid & 63, part = tid >> 6;
    float acc = 0.f;
    for (int e = part; e < Te; e += 4)
        acc = fmaf(tt[((size_t)b * Te + e) * 64 + d], s_prob[e], acc);
    s_tmp[tid] = acc; __syncthreads();
    if (tid < 64)
        s_red[tid] = (s_tmp[tid] + s_tmp[tid + 64] + s_tmp[tid + 128] + s_tmp[tid + 192]) * inv;
    __syncthreads();

    if (tid < 128) {
        float a = hb[tid];
        #pragma unroll 8
        for (int k = 0; k < 64; k++) a = fmaf(s_red[k], hw[tid * 64 + k], a);
        s_h[tid] = fmaxf(a, 0.f);
    }
    __syncthreads();

    if (tid == 0) {
        float l0 = cb[0], l1 = cb[1];
        for (int j = 0; j < 128; j++) {
            l0 = fmaf(s_h[j], cw[j], l0);
            l1 = fmaf(s_h[j], cw[128 + j], l1);
        }
        float mm = fmaxf(l0, l1);
        float e0 = expf(l0 - mm), e1 = expf(l1 - mm);
        float s = e0 + e1;
        out[b * 2 + 0] = e0 / s;
        out[b * 2 + 1] = e1 / s;
    }
}

// ---------------- host driver ----------------
extern "C" void kernel_launch(void* const* d_in, const int* in_sizes, int n_in,
                              void* d_out, int out_size)
{
    (void)in_sizes; (void)n_in; (void)out_size;

    const float* evaluation = (const float*)d_in[0];
    const float* templ      = (const float*)d_in[1];
    const float* e_w1 = (const float*)d_in[2];  const float* e_b1 = (const float*)d_in[3];
    const float* e_w2 = (const float*)d_in[4];  const float* e_b2 = (const float*)d_in[5];
    const float* e_w3 = (const float*)d_in[6];  const float* e_b3 = (const float*)d_in[7];
    const float* el_w = (const float*)d_in[8];  const float* el_b = (const float*)d_in[9];
    const float* eg_wih = (const float*)d_in[10]; const float* eg_whh = (const float*)d_in[11];
    const float* eg_bih = (const float*)d_in[12]; const float* eg_bhh = (const float*)d_in[13];
    const float* t_w1 = (const float*)d_in[14]; const float* t_b1 = (const float*)d_in[15];
    const float* t_w2 = (const float*)d_in[16]; const float* t_b2 = (const float*)d_in[17];
    const float* t_w3 = (const float*)d_in[18]; const float* t_b3 = (const float*)d_in[19];
    const float* tl_w = (const float*)d_in[20]; const float* tl_b = (const float*)d_in[21];
    const float* tg_wih = (const float*)d_in[22]; const float* tg_whh = (const float*)d_in[23];
    const float* tg_bih = (const float*)d_in[24]; const float* tg_bhh = (const float*)d_in[25];
    const float* a_w = (const float*)d_in[26]; const float* a_b = (const float*)d_in[27];
    const float* h_w = (const float*)d_in[28]; const float* h_b = (const float*)d_in[29];
    const float* c_w = (const float*)d_in[30]; const float* c_b = (const float*)d_in[31];

    __nv_bfloat16 *ex1h, *ex1l, *ex2h, *ex2l, *tx1h, *tx1l, *tx2h, *tx2l;
    uint2 *ewf2h, *ewf2l, *ewf3h, *ewf3l, *twf2h, *twf2l, *twf3h, *twf3l;
    float *ec3, *epool, *elin, *tc3, *tpool, *tlin;
    float *pge, *pgt, *psc, *ptt;
    cudaGetSymbolAddress((void**)&ex1h, g_x1h);  cudaGetSymbolAddress((void**)&ex1l, g_x1l);
    cudaGetSymbolAddress((void**)&ex2h, g_x2h);  cudaGetSymbolAddress((void**)&ex2l, g_x2l);
    cudaGetSymbolAddress((void**)&tx1h, t_x1h);  cudaGetSymbolAddress((void**)&tx1l, t_x1l);
    cudaGetSymbolAddress((void**)&tx2h, t_x2h);  cudaGetSymbolAddress((void**)&tx2l, t_x2l);
    cudaGetSymbolAddress((void**)&ewf2h, g_wf2h); cudaGetSymbolAddress((void**)&ewf2l, g_wf2l);
    cudaGetSymbolAddress((void**)&ewf3h, g_wf3h); cudaGetSymbolAddress((void**)&ewf3l, g_wf3l);
    cudaGetSymbolAddress((void**)&twf2h, t_wf2h); cudaGetSymbolAddress((void**)&twf2l, t_wf2l);
    cudaGetSymbolAddress((void**)&twf3h, t_wf3h); cudaGetSymbolAddress((void**)&twf3l, t_wf3l);
    cudaGetSymbolAddress((void**)&ec3,  g_c3);   cudaGetSymbolAddress((void**)&tc3,  t_c3);
    cudaGetSymbolAddress((void**)&epool, g_pool); cudaGetSymbolAddress((void**)&tpool, t_pool);
    cudaGetSymbolAddress((void**)&elin, g_lin);  cudaGetSymbolAddress((void**)&tlin, t_lin);
    cudaGetSymbolAddress((void**)&pge,  g_gru_e);
    cudaGetSymbolAddress((void**)&pgt,  g_gru_t);
    cudaGetSymbolAddress((void**)&psc,  g_scores);
    cudaGetSymbolAddress((void**)&ptt,  g_tt);

    // widths: eval 2048 -> 2044/2040/2036/2032 ; template 1040 -> 1036/1032/1028/1024
    prep_wfrag_kernel<<<(3200 + 255) / 256, 256>>>(e_w2, ewf2h, ewf2l, 16, 32);
    prep_wfrag_kernel<<<(3200 + 255) / 256, 256>>>(t_w2, twf2h, twf2l, 16, 32);
    prep_wfrag_kernel<<<(12800 + 255) / 256, 256>>>(e_w3, ewf3h, ewf3l, 32, 64);
    prep_wfrag_kernel<<<(12800 + 255) / 256, 256>>>(t_w3, twf3h, twf3l, 32, 64);

    conv1_merged_kernel<<<dim3(32, 16, 8), dim3(16, 8)>>>(
        evaluation, templ, e_w1, t_w1, e_b1, t_b1,
        ex1h, ex1l, tx1h, tx1l, 2048, 2044, 1040, 1036);

    conv5x5_tc_kernel<16, 32, false><<<dim3(32, 30, 8), 256>>>(
        ex1h, ex1l, tx1h, tx1l, ewf2h, ewf2l, twf2h, twf2l, e_b2, t_b2,
        nullptr, nullptr, ex2h, ex2l, tx2h, tx2l,
        124, 120, 2044, 2040, 1036, 1032);

    conv5x5_tc_kernel<32, 64, true><<<dim3(32, 29, 8), 256>>>(
        ex2h, ex2l, tx2h, tx2l, ewf3h, ewf3l, twf3h, twf3l, e_b3, t_b3,
        ec3, tc3, nullptr, nullptr, nullptr, nullptr,
        120, 116, 2040, 2036, 1032, 1028);

    const int n40 = (4 * 64 * 58 * 2032) / 4;
    const int n41 = (4 * 64 * 58 * 1024) / 4;
    maxpool_merged_kernel<<<(n40 + n41 + 255) / 256, 256>>>(
        ec3, epool, 2036, 2032, n40, tc3, tpool, 1028, 1024, n41);

    gemm_nt64_merged_kernel<<<127 + 64, 256>>>(
        epool, el_w, el_b, elin, tpool, tl_w, tl_b, tlin, 127, 3712);

    gru_merged_kernel<<<508 + 256, dim3(64, 4)>>>(
        elin, eg_wih, eg_whh, eg_bih, eg_bhh, pge, 2032, 508,
        tlin, tg_wih, tg_whh, tg_bih, tg_bhh, pgt, 1024);

    const int Tt = 1024, Te = 2032;
    scores_softmax_kernel<<<dim3(Tt / 4, 4), 256>>>(pgt, pge, psc, Tt, Te);
    gemm_tt_kernel<<<dim3((Te + 63) / 64, 4), 256>>>(psc, pgt, pge, ptt, Tt, Te);
    final_kernel<<<4, 256>>>(ptt, pge, a_w, a_b, h_w, h_b, c_w, c_b,
                             (float*)d_out, Te);
}